// round 6
// baseline (speedup 1.0000x reference)
#include <cuda_runtime.h>

// ---------------------------------------------------------------------------
// Problem constants: B=4, S=2048, C=1024, H=16, D=64
// ---------------------------------------------------------------------------
#define S_   2048
#define C_   1024
#define H_   16
#define D_   64
#define M_   8192           // B*S rows

// Scratch (static device globals; allocation-free per harness rules)
__device__ float g_qkv[(size_t)M_ * 3 * C_];            // 96 MB: (B,S,3,H,D)
__device__ float g_ropeT[(size_t)64 * 2 * D_ * S_];     // 64 MB: [bh][t][d][s]
__device__ float g_attn[(size_t)M_ * C_];               // 32 MB: (B,S,C)

// ---------------------------------------------------------------------------
// f32x2 packed helpers (Blackwell dual fp32 path — only reachable via PTX)
// ---------------------------------------------------------------------------
__device__ __forceinline__ unsigned long long pack2(float lo, float hi) {
    unsigned long long r;
    asm("mov.b64 %0, {%1, %2};" : "=l"(r) : "f"(lo), "f"(hi));
    return r;
}
__device__ __forceinline__ void unpack2(unsigned long long v, float& lo, float& hi) {
    asm("mov.b64 {%0, %1}, %2;" : "=f"(lo), "=f"(hi) : "l"(v));
}
__device__ __forceinline__ unsigned long long ffma2(unsigned long long a,
                                                    unsigned long long b,
                                                    unsigned long long c) {
    unsigned long long d;
    asm("fma.rn.f32x2 %0, %1, %2, %3;" : "=l"(d) : "l"(a), "l"(b), "l"(c));
    return d;
}
__device__ __forceinline__ unsigned long long fmul2(unsigned long long a,
                                                    unsigned long long b) {
    unsigned long long d;
    asm("mul.rn.f32x2 %0, %1, %2;" : "=l"(d) : "l"(a), "l"(b));
    return d;
}

// ---------------------------------------------------------------------------
// GEMM: C[m][n] = sum_k A[m][k]*W[n][k] + bias[n]     (unchanged — ~peak)
// ---------------------------------------------------------------------------
__global__ __launch_bounds__(256, 2)
void gemm_nt_bias(const float* __restrict__ A, const float* __restrict__ W,
                  const float* __restrict__ bias, float* __restrict__ Cout,
                  int N, int K)
{
    __shared__ float As[2][8][132];
    __shared__ float Bs[2][8][132];

    const int tid  = threadIdx.x;
    const int tx   = tid & 15;
    const int ty   = tid >> 4;
    const int lrow = tid >> 1;
    const int lk4  = (tid & 1) * 4;

    const int m0 = blockIdx.y * 128;
    const int n0 = blockIdx.x * 128;

    const float* Ap = A + (size_t)(m0 + lrow) * K + lk4;
    const float* Wp = W + (size_t)(n0 + lrow) * K + lk4;

    {
        float4 av = *(const float4*)Ap;
        float4 wv = *(const float4*)Wp;
        As[0][lk4 + 0][lrow] = av.x; As[0][lk4 + 1][lrow] = av.y;
        As[0][lk4 + 2][lrow] = av.z; As[0][lk4 + 3][lrow] = av.w;
        Bs[0][lk4 + 0][lrow] = wv.x; Bs[0][lk4 + 1][lrow] = wv.y;
        Bs[0][lk4 + 2][lrow] = wv.z; Bs[0][lk4 + 3][lrow] = wv.w;
    }
    __syncthreads();

    unsigned long long acc[8][4];
#pragma unroll
    for (int i = 0; i < 8; ++i) {
        acc[i][0] = 0ull; acc[i][1] = 0ull; acc[i][2] = 0ull; acc[i][3] = 0ull;
    }

    const int nk = K >> 3;
    for (int kt = 0; kt < nk; ++kt) {
        const int buf = kt & 1;
        float4 avn, wvn;
        const bool has_next = (kt + 1 < nk);
        if (has_next) {
            avn = *(const float4*)(Ap + (size_t)(kt + 1) * 8);
            wvn = *(const float4*)(Wp + (size_t)(kt + 1) * 8);
        }
#pragma unroll
        for (int k = 0; k < 8; ++k) {
            float4 a0 = *(const float4*)&As[buf][k][ty * 8];
            float4 a1 = *(const float4*)&As[buf][k][ty * 8 + 4];
            ulonglong2 kb0 = *(const ulonglong2*)&Bs[buf][k][tx * 4];
            ulonglong2 kb1 = *(const ulonglong2*)&Bs[buf][k][64 + tx * 4];
            float a[8] = {a0.x, a0.y, a0.z, a0.w, a1.x, a1.y, a1.z, a1.w};
#pragma unroll
            for (int i = 0; i < 8; ++i) {
                unsigned long long apk = pack2(a[i], a[i]);
                acc[i][0] = ffma2(apk, kb0.x, acc[i][0]);
                acc[i][1] = ffma2(apk, kb0.y, acc[i][1]);
                acc[i][2] = ffma2(apk, kb1.x, acc[i][2]);
                acc[i][3] = ffma2(apk, kb1.y, acc[i][3]);
            }
        }
        if (has_next) {
            const int nb = buf ^ 1;
            As[nb][lk4 + 0][lrow] = avn.x; As[nb][lk4 + 1][lrow] = avn.y;
            As[nb][lk4 + 2][lrow] = avn.z; As[nb][lk4 + 3][lrow] = avn.w;
            Bs[nb][lk4 + 0][lrow] = wvn.x; Bs[nb][lk4 + 1][lrow] = wvn.y;
            Bs[nb][lk4 + 2][lrow] = wvn.z; Bs[nb][lk4 + 3][lrow] = wvn.w;
            __syncthreads();
        }
    }

    float4 bb0 = *(const float4*)&bias[n0 + tx * 4];
    float4 bb1 = *(const float4*)&bias[n0 + 64 + tx * 4];
#pragma unroll
    for (int i = 0; i < 8; ++i) {
        float c0, c1, c2, c3, c4, c5, c6, c7;
        unpack2(acc[i][0], c0, c1);
        unpack2(acc[i][1], c2, c3);
        unpack2(acc[i][2], c4, c5);
        unpack2(acc[i][3], c6, c7);
        float* cp = Cout + (size_t)(m0 + ty * 8 + i) * N + n0;
        *(float4*)(cp + tx * 4) =
            make_float4(c0 + bb0.x, c1 + bb0.y, c2 + bb0.z, c3 + bb0.w);
        *(float4*)(cp + 64 + tx * 4) =
            make_float4(c4 + bb1.x, c5 + bb1.y, c6 + bb1.z, c7 + bb1.w);
    }
}

// ---------------------------------------------------------------------------
// RoPE + transpose. q (t=0) additionally scaled by D^-0.5 = 0.125 so the
// flash kernel's scores need no explicit scale.
// ---------------------------------------------------------------------------
__global__ __launch_bounds__(256)
void rope_t_kernel(const float* __restrict__ qkv,
                   const float* __restrict__ cosp,
                   const float* __restrict__ sinp,
                   float* __restrict__ ropeT)
{
    extern __shared__ float rs[];
    float* Tx = rs;
    float* Tc = rs + 64 * 67;
    float* Ts = rs + 2 * 64 * 67;

    const int tid = threadIdx.x;
    const int s0  = blockIdx.x * 64;
    const int bh  = blockIdx.y;
    const int b   = bh >> 4;
    const int h   = bh & 15;
    const int t   = blockIdx.z;
    const float qs = (t == 0) ? 0.125f : 1.0f;

#pragma unroll
    for (int it = 0; it < 4; ++it) {
        int idx = it * 256 + tid;
        int sl  = idx >> 4;
        int dc  = (idx & 15) * 4;
        size_t bs = (size_t)(b * S_ + s0 + sl);
        float4 xv = *(const float4*)(qkv + (bs * 3 + t) * C_ + h * D_ + dc);
        float4 cv = *(const float4*)(cosp + bs * D_ + dc);
        float4 sv = *(const float4*)(sinp + bs * D_ + dc);
        Tx[sl * 67 + dc + 0] = xv.x; Tx[sl * 67 + dc + 1] = xv.y;
        Tx[sl * 67 + dc + 2] = xv.z; Tx[sl * 67 + dc + 3] = xv.w;
        Tc[sl * 67 + dc + 0] = cv.x; Tc[sl * 67 + dc + 1] = cv.y;
        Tc[sl * 67 + dc + 2] = cv.z; Tc[sl * 67 + dc + 3] = cv.w;
        Ts[sl * 67 + dc + 0] = sv.x; Ts[sl * 67 + dc + 1] = sv.y;
        Ts[sl * 67 + dc + 2] = sv.z; Ts[sl * 67 + dc + 3] = sv.w;
    }
    __syncthreads();

#pragma unroll
    for (int it = 0; it < 4; ++it) {
        int idx = it * 256 + tid;
        int d   = idx >> 4;
        int sc  = (idx & 15) * 4;
        float out[4];
#pragma unroll
        for (int j = 0; j < 4; ++j) {
            int sl = sc + j;
            float x0 = Tx[sl * 67 + d];
            float x1 = Tx[sl * 67 + (d ^ 32)];
            float c  = Tc[sl * 67 + d];
            float sn = Ts[sl * 67 + d];
            float rh = (d < 32) ? -x1 : x1;
            out[j] = qs * fmaf(x0, c, rh * sn);
        }
        *(float4*)(ropeT + ((size_t)(bh * 2 + t) * D_ + d) * S_ + s0 + sc) =
            make_float4(out[0], out[1], out[2], out[3]);
    }
}

// ---------------------------------------------------------------------------
// Flash attention v2: 512 threads/CTA (16 warps -> 4/SMSP), fp32.
// Grid (S/128, B*H). smem: QT[64][132], KT[64][132], Vs[128][68],
// Ps[128][132], Sa[128] (alpha / 1/l exchange).
// QK phase:  thread = (cx = tid&15, ry = tid>>4): rows ry*4..+3,
//            keys cx*4..+3 and 64+cx*4..+3. 16-lane shfl row reductions.
// PV phase:  thread = (dx = tid&7, py = tid>>3): rows py*2,+1,
//            dims dx*4..+3 and 32+dx*4..+3.
// K/V operands read as ulonglong2 (no packing); only broadcast side packs.
// Score scale pre-folded into q by rope_t_kernel.
// ---------------------------------------------------------------------------
#define FLASH_SMEM_FLOATS (64*132 + 64*132 + 128*68 + 128*132 + 128)
#define FLASH_SMEM_BYTES  (FLASH_SMEM_FLOATS * 4)

__global__ __launch_bounds__(512, 1)
void flash_kernel(const float* __restrict__ ropeT,
                  const float* __restrict__ qkv,
                  float* __restrict__ attn)
{
    extern __shared__ float sm[];
    float* QT = sm;                         // [64][132]
    float* KT = sm + 64 * 132;              // [64][132]
    float* Vs = sm + 2 * 64 * 132;          // [128][68]
    float* Ps = sm + 2 * 64 * 132 + 128 * 68;   // [128][132]
    float* Sa = Ps + 128 * 132;             // [128]

    const int tid = threadIdx.x;
    const int cx  = tid & 15;               // QK key group
    const int ry  = tid >> 4;               // QK row group (0..31)
    const int dx  = tid & 7;                // PV dim group
    const int py  = tid >> 3;               // PV row group (0..63)
    const int qb  = blockIdx.x;
    const int bh  = blockIdx.y;
    const int b   = bh >> 4;
    const int h   = bh & 15;
    const int q0  = qb * 128;

    // stage QT (coalesced; q already scaled by 0.125)
    const float* qsrc = ropeT + (size_t)(bh * 2 + 0) * D_ * S_;
#pragma unroll
    for (int it = 0; it < 4; ++it) {
        int idx = it * 512 + tid;            // 0..2047
        int d   = idx >> 5;                  // 0..63
        int sc  = (idx & 31) * 4;            // 0..124
        float4 v = *(const float4*)(qsrc + (size_t)d * S_ + q0 + sc);
        *(float4*)&QT[d * 132 + sc] = v;
    }

    float m_i[4], l_i[4];
    unsigned long long o[2][4];
#pragma unroll
    for (int i = 0; i < 4; ++i) { m_i[i] = -1.0e30f; l_i[i] = 0.0f; }
#pragma unroll
    for (int r = 0; r < 2; ++r) {
        o[r][0] = 0ull; o[r][1] = 0ull; o[r][2] = 0ull; o[r][3] = 0ull;
    }

    const float* ksrc = ropeT + (size_t)(bh * 2 + 1) * D_ * S_;

    for (int kb = 0; kb < 16; ++kb) {
        __syncthreads();   // prior PV done with KT/Vs/Ps/Sa; covers QT on kb=0
        const int k0 = kb * 128;

        // stage KT
#pragma unroll
        for (int it = 0; it < 4; ++it) {
            int idx = it * 512 + tid;
            int d   = idx >> 5;
            int sc  = (idx & 31) * 4;
            float4 v = *(const float4*)(ksrc + (size_t)d * S_ + k0 + sc);
            *(float4*)&KT[d * 132 + sc] = v;
        }
        // stage Vs (row-major from g_qkv, t=2)
#pragma unroll
        for (int it = 0; it < 4; ++it) {
            int idx = it * 512 + tid;
            int sl  = idx >> 4;              // 0..127
            int dc  = (idx & 15) * 4;        // 0..60
            float4 v = *(const float4*)(qkv +
                ((size_t)(b * S_ + k0 + sl) * 3 + 2) * C_ + h * D_ + dc);
            *(float4*)&Vs[sl * 68 + dc] = v;
        }
        __syncthreads();

        // ---- S = Q @ K^T : 4 rows x 8 keys per thread ----
        unsigned long long acc[4][4];
#pragma unroll
        for (int i = 0; i < 4; ++i) {
            acc[i][0] = 0ull; acc[i][1] = 0ull;
            acc[i][2] = 0ull; acc[i][3] = 0ull;
        }
#pragma unroll 4
        for (int d = 0; d < 64; ++d) {
            float4 qv = *(const float4*)&QT[d * 132 + ry * 4];
            ulonglong2 ka = *(const ulonglong2*)&KT[d * 132 + cx * 4];
            ulonglong2 kc = *(const ulonglong2*)&KT[d * 132 + 64 + cx * 4];
            float qarr[4] = {qv.x, qv.y, qv.z, qv.w};
#pragma unroll
            for (int i = 0; i < 4; ++i) {
                unsigned long long qq = pack2(qarr[i], qarr[i]);
                acc[i][0] = ffma2(qq, ka.x, acc[i][0]);
                acc[i][1] = ffma2(qq, ka.y, acc[i][1]);
                acc[i][2] = ffma2(qq, kc.x, acc[i][2]);
                acc[i][3] = ffma2(qq, kc.y, acc[i][3]);
            }
        }

        // ---- online softmax (per thread: 4 rows x 8 keys) ----
#pragma unroll
        for (int i = 0; i < 4; ++i) {
            float s0, s1, s2, s3, s4, s5, s6, s7;
            unpack2(acc[i][0], s0, s1);
            unpack2(acc[i][1], s2, s3);
            unpack2(acc[i][2], s4, s5);
            unpack2(acc[i][3], s6, s7);
            float mx = fmaxf(fmaxf(fmaxf(s0, s1), fmaxf(s2, s3)),
                             fmaxf(fmaxf(s4, s5), fmaxf(s6, s7)));
#pragma unroll
            for (int off = 1; off < 16; off <<= 1)
                mx = fmaxf(mx, __shfl_xor_sync(0xffffffffu, mx, off));
            float mnew  = fmaxf(m_i[i], mx);
            float alpha = __expf(m_i[i] - mnew);
            m_i[i] = mnew;
            float p0 = __expf(s0 - mnew), p1 = __expf(s1 - mnew);
            float p2 = __expf(s2 - mnew), p3 = __expf(s3 - mnew);
            float p4 = __expf(s4 - mnew), p5 = __expf(s5 - mnew);
            float p6 = __expf(s6 - mnew), p7 = __expf(s7 - mnew);
            float lsum = ((p0 + p1) + (p2 + p3)) + ((p4 + p5) + (p6 + p7));
#pragma unroll
            for (int off = 1; off < 16; off <<= 1)
                lsum += __shfl_xor_sync(0xffffffffu, lsum, off);
            l_i[i] = l_i[i] * alpha + lsum;
            int r = ry * 4 + i;
            if (cx == 0) Sa[r] = alpha;
            *(float4*)&Ps[r * 132 + cx * 4]      = make_float4(p0, p1, p2, p3);
            *(float4*)&Ps[r * 132 + 64 + cx * 4] = make_float4(p4, p5, p6, p7);
        }
        __syncthreads();

        // ---- O = O*alpha + P @ V : 2 rows x 8 split dims per thread ----
        {
            unsigned long long a0 = pack2(Sa[py * 2],     Sa[py * 2]);
            unsigned long long a1 = pack2(Sa[py * 2 + 1], Sa[py * 2 + 1]);
#pragma unroll
            for (int j = 0; j < 4; ++j) {
                o[0][j] = fmul2(o[0][j], a0);
                o[1][j] = fmul2(o[1][j], a1);
            }
        }
#pragma unroll 2
        for (int kc = 0; kc < 128; kc += 4) {
            ulonglong2 va[4], vb[4];
#pragma unroll
            for (int k = 0; k < 4; ++k) {
                va[k] = *(const ulonglong2*)&Vs[(kc + k) * 68 + dx * 4];
                vb[k] = *(const ulonglong2*)&Vs[(kc + k) * 68 + 32 + dx * 4];
            }
            float4 pr0 = *(const float4*)&Ps[(py * 2) * 132 + kc];
            float4 pr1 = *(const float4*)&Ps[(py * 2 + 1) * 132 + kc];
            float p0a[4] = {pr0.x, pr0.y, pr0.z, pr0.w};
            float p1a[4] = {pr1.x, pr1.y, pr1.z, pr1.w};
#pragma unroll
            for (int k = 0; k < 4; ++k) {
                unsigned long long pd0 = pack2(p0a[k], p0a[k]);
                unsigned long long pd1 = pack2(p1a[k], p1a[k]);
                o[0][0] = ffma2(pd0, va[k].x, o[0][0]);
                o[0][1] = ffma2(pd0, va[k].y, o[0][1]);
                o[0][2] = ffma2(pd0, vb[k].x, o[0][2]);
                o[0][3] = ffma2(pd0, vb[k].y, o[0][3]);
                o[1][0] = ffma2(pd1, va[k].x, o[1][0]);
                o[1][1] = ffma2(pd1, va[k].y, o[1][1]);
                o[1][2] = ffma2(pd1, vb[k].x, o[1][2]);
                o[1][3] = ffma2(pd1, vb[k].y, o[1][3]);
            }
        }
    }

    // ---- publish 1/l, then normalize + store ----
    __syncthreads();           // last PV finished reading Sa (alpha)
    if (cx == 0) {
#pragma unroll
        for (int i = 0; i < 4; ++i) Sa[ry * 4 + i] = 1.0f / l_i[i];
    }
    __syncthreads();

#pragma unroll
    for (int r = 0; r < 2; ++r) {
        float inv = Sa[py * 2 + r];
        float o0, o1, o2, o3, o4, o5, o6, o7;
        unpack2(o[r][0], o0, o1);
        unpack2(o[r][1], o2, o3);
        unpack2(o[r][2], o4, o5);
        unpack2(o[r][3], o6, o7);
        size_t row = (size_t)(b * S_ + q0 + py * 2 + r);
        float* op = attn + row * C_ + h * D_;
        *(float4*)(op + dx * 4) =
            make_float4(o0 * inv, o1 * inv, o2 * inv, o3 * inv);
        *(float4*)(op + 32 + dx * 4) =
            make_float4(o4 * inv, o5 * inv, o6 * inv, o7 * inv);
    }
}

// ---------------------------------------------------------------------------
// Launch
// ---------------------------------------------------------------------------
extern "C" void kernel_launch(void* const* d_in, const int* in_sizes, int n_in,
                              void* d_out, int out_size)
{
    (void)in_sizes; (void)n_in; (void)out_size;
    const float* hidden = (const float*)d_in[0];
    const float* cosp   = (const float*)d_in[1];
    const float* sinp   = (const float*)d_in[2];
    const float* qkv_w  = (const float*)d_in[3];
    const float* qkv_b  = (const float*)d_in[4];
    const float* proj_w = (const float*)d_in[5];
    const float* proj_b = (const float*)d_in[6];
    float* out = (float*)d_out;

    float *qkv_s = nullptr, *ropeT_s = nullptr, *attn_s = nullptr;
    cudaGetSymbolAddress((void**)&qkv_s,   g_qkv);
    cudaGetSymbolAddress((void**)&ropeT_s, g_ropeT);
    cudaGetSymbolAddress((void**)&attn_s,  g_attn);

    const int rope_smem = 3 * 64 * 67 * 4;  // 51456
    cudaFuncSetAttribute(rope_t_kernel,
                         cudaFuncAttributeMaxDynamicSharedMemorySize, rope_smem);
    cudaFuncSetAttribute(flash_kernel,
                         cudaFuncAttributeMaxDynamicSharedMemorySize, FLASH_SMEM_BYTES);

    // 1) QKV GEMM
    gemm_nt_bias<<<dim3(3 * C_ / 128, M_ / 128), 256>>>(
        hidden, qkv_w, qkv_b, qkv_s, 3 * C_, C_);

    // 2) RoPE + transpose (q pre-scaled by D^-0.5)
    rope_t_kernel<<<dim3(S_ / 64, 64, 2), 256, rope_smem>>>(
        qkv_s, cosp, sinp, ropeT_s);

    // 3) Flash attention v2 (512 threads)
    flash_kernel<<<dim3(S_ / 128, 64), 512, FLASH_SMEM_BYTES>>>(
        ropeT_s, qkv_s, attn_s);

    // 4) Proj GEMM
    gemm_nt_bias<<<dim3(C_ / 128, M_ / 128), 256>>>(
        attn_s, proj_w, proj_b, out, C_, C_);
}

// round 7
// speedup vs baseline: 1.1767x; 1.1767x over previous
#include <cuda_runtime.h>

// ---------------------------------------------------------------------------
// Problem constants: B=4, S=2048, C=1024, H=16, D=64
// ---------------------------------------------------------------------------
#define S_   2048
#define C_   1024
#define H_   16
#define D_   64
#define M_   8192           // B*S rows

// Scratch (static device globals; allocation-free per harness rules)
__device__ float g_qkv[(size_t)M_ * 3 * C_];            // 96 MB: (B,S,3,H,D)
__device__ float g_ropeT[(size_t)64 * 2 * D_ * S_];     // 64 MB: [bh][t][d][s]
__device__ float g_attn[(size_t)M_ * C_];               // 32 MB: (B,S,C)

// ---------------------------------------------------------------------------
// f32x2 packed helpers (Blackwell dual fp32 path — only reachable via PTX)
// ---------------------------------------------------------------------------
__device__ __forceinline__ unsigned long long pack2(float lo, float hi) {
    unsigned long long r;
    asm("mov.b64 %0, {%1, %2};" : "=l"(r) : "f"(lo), "f"(hi));
    return r;
}
__device__ __forceinline__ void unpack2(unsigned long long v, float& lo, float& hi) {
    asm("mov.b64 {%0, %1}, %2;" : "=f"(lo), "=f"(hi) : "l"(v));
}
__device__ __forceinline__ unsigned long long ffma2(unsigned long long a,
                                                    unsigned long long b,
                                                    unsigned long long c) {
    unsigned long long d;
    asm("fma.rn.f32x2 %0, %1, %2, %3;" : "=l"(d) : "l"(a), "l"(b), "l"(c));
    return d;
}
__device__ __forceinline__ unsigned long long fmul2(unsigned long long a,
                                                    unsigned long long b) {
    unsigned long long d;
    asm("mul.rn.f32x2 %0, %1, %2;" : "=l"(d) : "l"(a), "l"(b));
    return d;
}

// ---------------------------------------------------------------------------
// GEMM: C[m][n] = sum_k A[m][k]*W[n][k] + bias[n]   (FROZEN — at fp32 peak)
// ---------------------------------------------------------------------------
__global__ __launch_bounds__(256, 2)
void gemm_nt_bias(const float* __restrict__ A, const float* __restrict__ W,
                  const float* __restrict__ bias, float* __restrict__ Cout,
                  int N, int K)
{
    __shared__ float As[2][8][132];
    __shared__ float Bs[2][8][132];

    const int tid  = threadIdx.x;
    const int tx   = tid & 15;
    const int ty   = tid >> 4;
    const int lrow = tid >> 1;
    const int lk4  = (tid & 1) * 4;

    const int m0 = blockIdx.y * 128;
    const int n0 = blockIdx.x * 128;

    const float* Ap = A + (size_t)(m0 + lrow) * K + lk4;
    const float* Wp = W + (size_t)(n0 + lrow) * K + lk4;

    {
        float4 av = *(const float4*)Ap;
        float4 wv = *(const float4*)Wp;
        As[0][lk4 + 0][lrow] = av.x; As[0][lk4 + 1][lrow] = av.y;
        As[0][lk4 + 2][lrow] = av.z; As[0][lk4 + 3][lrow] = av.w;
        Bs[0][lk4 + 0][lrow] = wv.x; Bs[0][lk4 + 1][lrow] = wv.y;
        Bs[0][lk4 + 2][lrow] = wv.z; Bs[0][lk4 + 3][lrow] = wv.w;
    }
    __syncthreads();

    unsigned long long acc[8][4];
#pragma unroll
    for (int i = 0; i < 8; ++i) {
        acc[i][0] = 0ull; acc[i][1] = 0ull; acc[i][2] = 0ull; acc[i][3] = 0ull;
    }

    const int nk = K >> 3;
    for (int kt = 0; kt < nk; ++kt) {
        const int buf = kt & 1;
        float4 avn, wvn;
        const bool has_next = (kt + 1 < nk);
        if (has_next) {
            avn = *(const float4*)(Ap + (size_t)(kt + 1) * 8);
            wvn = *(const float4*)(Wp + (size_t)(kt + 1) * 8);
        }
#pragma unroll
        for (int k = 0; k < 8; ++k) {
            float4 a0 = *(const float4*)&As[buf][k][ty * 8];
            float4 a1 = *(const float4*)&As[buf][k][ty * 8 + 4];
            ulonglong2 kb0 = *(const ulonglong2*)&Bs[buf][k][tx * 4];
            ulonglong2 kb1 = *(const ulonglong2*)&Bs[buf][k][64 + tx * 4];
            float a[8] = {a0.x, a0.y, a0.z, a0.w, a1.x, a1.y, a1.z, a1.w};
#pragma unroll
            for (int i = 0; i < 8; ++i) {
                unsigned long long apk = pack2(a[i], a[i]);
                acc[i][0] = ffma2(apk, kb0.x, acc[i][0]);
                acc[i][1] = ffma2(apk, kb0.y, acc[i][1]);
                acc[i][2] = ffma2(apk, kb1.x, acc[i][2]);
                acc[i][3] = ffma2(apk, kb1.y, acc[i][3]);
            }
        }
        if (has_next) {
            const int nb = buf ^ 1;
            As[nb][lk4 + 0][lrow] = avn.x; As[nb][lk4 + 1][lrow] = avn.y;
            As[nb][lk4 + 2][lrow] = avn.z; As[nb][lk4 + 3][lrow] = avn.w;
            Bs[nb][lk4 + 0][lrow] = wvn.x; Bs[nb][lk4 + 1][lrow] = wvn.y;
            Bs[nb][lk4 + 2][lrow] = wvn.z; Bs[nb][lk4 + 3][lrow] = wvn.w;
            __syncthreads();
        }
    }

    float4 bb0 = *(const float4*)&bias[n0 + tx * 4];
    float4 bb1 = *(const float4*)&bias[n0 + 64 + tx * 4];
#pragma unroll
    for (int i = 0; i < 8; ++i) {
        float c0, c1, c2, c3, c4, c5, c6, c7;
        unpack2(acc[i][0], c0, c1);
        unpack2(acc[i][1], c2, c3);
        unpack2(acc[i][2], c4, c5);
        unpack2(acc[i][3], c6, c7);
        float* cp = Cout + (size_t)(m0 + ty * 8 + i) * N + n0;
        *(float4*)(cp + tx * 4) =
            make_float4(c0 + bb0.x, c1 + bb0.y, c2 + bb0.z, c3 + bb0.w);
        *(float4*)(cp + 64 + tx * 4) =
            make_float4(c4 + bb1.x, c5 + bb1.y, c6 + bb1.z, c7 + bb1.w);
    }
}

// ---------------------------------------------------------------------------
// RoPE + transpose. q (t=0) pre-scaled by D^-0.5 = 0.125.
// ---------------------------------------------------------------------------
__global__ __launch_bounds__(256)
void rope_t_kernel(const float* __restrict__ qkv,
                   const float* __restrict__ cosp,
                   const float* __restrict__ sinp,
                   float* __restrict__ ropeT)
{
    extern __shared__ float rs[];
    float* Tx = rs;
    float* Tc = rs + 64 * 67;
    float* Ts = rs + 2 * 64 * 67;

    const int tid = threadIdx.x;
    const int s0  = blockIdx.x * 64;
    const int bh  = blockIdx.y;
    const int b   = bh >> 4;
    const int h   = bh & 15;
    const int t   = blockIdx.z;
    const float qs = (t == 0) ? 0.125f : 1.0f;

#pragma unroll
    for (int it = 0; it < 4; ++it) {
        int idx = it * 256 + tid;
        int sl  = idx >> 4;
        int dc  = (idx & 15) * 4;
        size_t bs = (size_t)(b * S_ + s0 + sl);
        float4 xv = *(const float4*)(qkv + (bs * 3 + t) * C_ + h * D_ + dc);
        float4 cv = *(const float4*)(cosp + bs * D_ + dc);
        float4 sv = *(const float4*)(sinp + bs * D_ + dc);
        Tx[sl * 67 + dc + 0] = xv.x; Tx[sl * 67 + dc + 1] = xv.y;
        Tx[sl * 67 + dc + 2] = xv.z; Tx[sl * 67 + dc + 3] = xv.w;
        Tc[sl * 67 + dc + 0] = cv.x; Tc[sl * 67 + dc + 1] = cv.y;
        Tc[sl * 67 + dc + 2] = cv.z; Tc[sl * 67 + dc + 3] = cv.w;
        Ts[sl * 67 + dc + 0] = sv.x; Ts[sl * 67 + dc + 1] = sv.y;
        Ts[sl * 67 + dc + 2] = sv.z; Ts[sl * 67 + dc + 3] = sv.w;
    }
    __syncthreads();

#pragma unroll
    for (int it = 0; it < 4; ++it) {
        int idx = it * 256 + tid;
        int d   = idx >> 4;
        int sc  = (idx & 15) * 4;
        float out[4];
#pragma unroll
        for (int j = 0; j < 4; ++j) {
            int sl = sc + j;
            float x0 = Tx[sl * 67 + d];
            float x1 = Tx[sl * 67 + (d ^ 32)];
            float c  = Tc[sl * 67 + d];
            float sn = Ts[sl * 67 + d];
            float rh = (d < 32) ? -x1 : x1;
            out[j] = qs * fmaf(x0, c, rh * sn);
        }
        *(float4*)(ropeT + ((size_t)(bh * 2 + t) * D_ + d) * S_ + s0 + sc) =
            make_float4(out[0], out[1], out[2], out[3]);
    }
}

// ---------------------------------------------------------------------------
// Flash attention v3: BQ=128, BK=64, 256 threads, 2 CTAs/SM (103.4 KB smem).
// Unified row ownership: rows = (tid>>3)*4..+3 in BOTH QK and PV phases ->
// m/l/alpha stay in registers (no smem exchange).
// Thread tile: QK 4 rows x 8 keys (keys cx*4, 32+cx*4); PV 4 rows x 8 dims.
// smem: QT[64][132] (d-major Q), KT[64][68] (d-major K), Vs[64][68], Ps[128][68].
// K/V read as ulonglong2 (no packing); 1 pack per 4 ffma2 on broadcast side.
// Score scale pre-folded into q by rope_t_kernel.
// ---------------------------------------------------------------------------
#define FLASH_SMEM_FLOATS (64*132 + 64*68 + 64*68 + 128*68)
#define FLASH_SMEM_BYTES  (FLASH_SMEM_FLOATS * 4)   // 103,424 B

__global__ __launch_bounds__(256, 2)
void flash_kernel(const float* __restrict__ ropeT,
                  const float* __restrict__ qkv,
                  float* __restrict__ attn)
{
    extern __shared__ float sm[];
    float* QT = sm;                           // [64][132]
    float* KT = sm + 64 * 132;                // [64][68]
    float* Vs = sm + 64 * 132 + 64 * 68;      // [64][68]
    float* Ps = sm + 64 * 132 + 2 * 64 * 68;  // [128][68]

    const int tid = threadIdx.x;
    const int cx  = tid & 7;                  // key/dim group (0..7)
    const int ry  = tid >> 3;                 // row group (0..31), rows ry*4..+3
    const int qb  = blockIdx.x;
    const int bh  = blockIdx.y;
    const int b   = bh >> 4;
    const int h   = bh & 15;
    const int q0  = qb * 128;

    // stage QT (coalesced; q already scaled by 0.125)
    const float* qsrc = ropeT + (size_t)(bh * 2 + 0) * D_ * S_;
#pragma unroll
    for (int it = 0; it < 8; ++it) {
        int idx = it * 256 + tid;             // 0..2047
        int d   = idx >> 5;                   // 0..63
        int sc  = (idx & 31) * 4;             // 0..124
        float4 v = *(const float4*)(qsrc + (size_t)d * S_ + q0 + sc);
        *(float4*)&QT[d * 132 + sc] = v;
    }

    float m_i[4], l_i[4];
    unsigned long long o[4][4];               // 4 rows x 8 dims (4 f32x2 each)
#pragma unroll
    for (int i = 0; i < 4; ++i) {
        m_i[i] = -1.0e30f; l_i[i] = 0.0f;
        o[i][0] = 0ull; o[i][1] = 0ull; o[i][2] = 0ull; o[i][3] = 0ull;
    }

    const float* ksrc = ropeT + (size_t)(bh * 2 + 1) * D_ * S_;

    for (int kb = 0; kb < 32; ++kb) {
        __syncthreads();   // prev PV done with KT/Vs/Ps; covers QT on kb=0
        const int k0 = kb * 64;

        // stage KT: 64 d x 64 keys (d-major gmem, coalesced)
#pragma unroll
        for (int it = 0; it < 4; ++it) {
            int idx = it * 256 + tid;         // 0..1023
            int d   = idx >> 4;               // 0..63
            int sc  = (idx & 15) * 4;         // 0..60
            float4 v = *(const float4*)(ksrc + (size_t)d * S_ + k0 + sc);
            *(float4*)&KT[d * 68 + sc] = v;
        }
        // stage Vs: 64 keys x 64 dims (row-major from g_qkv, t=2)
#pragma unroll
        for (int it = 0; it < 4; ++it) {
            int idx = it * 256 + tid;
            int sl  = idx >> 4;               // 0..63
            int dc  = (idx & 15) * 4;         // 0..60
            float4 v = *(const float4*)(qkv +
                ((size_t)(b * S_ + k0 + sl) * 3 + 2) * C_ + h * D_ + dc);
            *(float4*)&Vs[sl * 68 + dc] = v;
        }
        __syncthreads();

        // ---- S = Q @ K^T : 4 rows x 8 keys per thread ----
        unsigned long long acc[4][4];
#pragma unroll
        for (int i = 0; i < 4; ++i) {
            acc[i][0] = 0ull; acc[i][1] = 0ull;
            acc[i][2] = 0ull; acc[i][3] = 0ull;
        }
#pragma unroll 4
        for (int d = 0; d < 64; ++d) {
            float4 qv = *(const float4*)&QT[d * 132 + ry * 4];
            ulonglong2 ka = *(const ulonglong2*)&KT[d * 68 + cx * 4];
            ulonglong2 kc = *(const ulonglong2*)&KT[d * 68 + 32 + cx * 4];
            float qarr[4] = {qv.x, qv.y, qv.z, qv.w};
#pragma unroll
            for (int i = 0; i < 4; ++i) {
                unsigned long long qq = pack2(qarr[i], qarr[i]);
                acc[i][0] = ffma2(qq, ka.x, acc[i][0]);
                acc[i][1] = ffma2(qq, ka.y, acc[i][1]);
                acc[i][2] = ffma2(qq, kc.x, acc[i][2]);
                acc[i][3] = ffma2(qq, kc.y, acc[i][3]);
            }
        }

        // ---- online softmax (4 rows; reduce over 8 lanes = 64 keys) ----
#pragma unroll
        for (int i = 0; i < 4; ++i) {
            float s0, s1, s2, s3, s4, s5, s6, s7;
            unpack2(acc[i][0], s0, s1);
            unpack2(acc[i][1], s2, s3);
            unpack2(acc[i][2], s4, s5);
            unpack2(acc[i][3], s6, s7);
            float mx = fmaxf(fmaxf(fmaxf(s0, s1), fmaxf(s2, s3)),
                             fmaxf(fmaxf(s4, s5), fmaxf(s6, s7)));
#pragma unroll
            for (int off = 1; off < 8; off <<= 1)
                mx = fmaxf(mx, __shfl_xor_sync(0xffffffffu, mx, off));
            float mnew  = fmaxf(m_i[i], mx);
            float alpha = __expf(m_i[i] - mnew);
            m_i[i] = mnew;
            float p0 = __expf(s0 - mnew), p1 = __expf(s1 - mnew);
            float p2 = __expf(s2 - mnew), p3 = __expf(s3 - mnew);
            float p4 = __expf(s4 - mnew), p5 = __expf(s5 - mnew);
            float p6 = __expf(s6 - mnew), p7 = __expf(s7 - mnew);
            float lsum = ((p0 + p1) + (p2 + p3)) + ((p4 + p5) + (p6 + p7));
#pragma unroll
            for (int off = 1; off < 8; off <<= 1)
                lsum += __shfl_xor_sync(0xffffffffu, lsum, off);
            l_i[i] = l_i[i] * alpha + lsum;
            // rescale O locally (alpha is register-resident)
            unsigned long long a2 = pack2(alpha, alpha);
            o[i][0] = fmul2(o[i][0], a2);
            o[i][1] = fmul2(o[i][1], a2);
            o[i][2] = fmul2(o[i][2], a2);
            o[i][3] = fmul2(o[i][3], a2);
            int r = ry * 4 + i;
            *(float4*)&Ps[r * 68 + cx * 4]      = make_float4(p0, p1, p2, p3);
            *(float4*)&Ps[r * 68 + 32 + cx * 4] = make_float4(p4, p5, p6, p7);
        }
        __syncthreads();

        // ---- O += P @ V : 4 rows x 8 dims per thread ----
#pragma unroll 2
        for (int kc = 0; kc < 64; kc += 4) {
            ulonglong2 va[4], vb[4];
#pragma unroll
            for (int k = 0; k < 4; ++k) {
                va[k] = *(const ulonglong2*)&Vs[(kc + k) * 68 + cx * 4];
                vb[k] = *(const ulonglong2*)&Vs[(kc + k) * 68 + 32 + cx * 4];
            }
#pragma unroll
            for (int i = 0; i < 4; ++i) {
                float4 pf = *(const float4*)&Ps[(ry * 4 + i) * 68 + kc];
                unsigned long long pd0 = pack2(pf.x, pf.x);
                unsigned long long pd1 = pack2(pf.y, pf.y);
                unsigned long long pd2 = pack2(pf.z, pf.z);
                unsigned long long pd3 = pack2(pf.w, pf.w);
                o[i][0] = ffma2(pd0, va[0].x, o[i][0]);
                o[i][1] = ffma2(pd0, va[0].y, o[i][1]);
                o[i][2] = ffma2(pd0, vb[0].x, o[i][2]);
                o[i][3] = ffma2(pd0, vb[0].y, o[i][3]);
                o[i][0] = ffma2(pd1, va[1].x, o[i][0]);
                o[i][1] = ffma2(pd1, va[1].y, o[i][1]);
                o[i][2] = ffma2(pd1, vb[1].x, o[i][2]);
                o[i][3] = ffma2(pd1, vb[1].y, o[i][3]);
                o[i][0] = ffma2(pd2, va[2].x, o[i][0]);
                o[i][1] = ffma2(pd2, va[2].y, o[i][1]);
                o[i][2] = ffma2(pd2, vb[2].x, o[i][2]);
                o[i][3] = ffma2(pd2, vb[2].y, o[i][3]);
                o[i][0] = ffma2(pd3, va[3].x, o[i][0]);
                o[i][1] = ffma2(pd3, va[3].y, o[i][1]);
                o[i][2] = ffma2(pd3, vb[3].x, o[i][2]);
                o[i][3] = ffma2(pd3, vb[3].y, o[i][3]);
            }
        }
    }

    // ---- normalize + store (l is register-resident) ----
#pragma unroll
    for (int i = 0; i < 4; ++i) {
        float inv = 1.0f / l_i[i];
        float o0, o1, o2, o3, o4, o5, o6, o7;
        unpack2(o[i][0], o0, o1);
        unpack2(o[i][1], o2, o3);
        unpack2(o[i][2], o4, o5);
        unpack2(o[i][3], o6, o7);
        size_t row = (size_t)(b * S_ + q0 + ry * 4 + i);
        float* op = attn + row * C_ + h * D_;
        *(float4*)(op + cx * 4) =
            make_float4(o0 * inv, o1 * inv, o2 * inv, o3 * inv);
        *(float4*)(op + 32 + cx * 4) =
            make_float4(o4 * inv, o5 * inv, o6 * inv, o7 * inv);
    }
}

// ---------------------------------------------------------------------------
// Launch
// ---------------------------------------------------------------------------
extern "C" void kernel_launch(void* const* d_in, const int* in_sizes, int n_in,
                              void* d_out, int out_size)
{
    (void)in_sizes; (void)n_in; (void)out_size;
    const float* hidden = (const float*)d_in[0];
    const float* cosp   = (const float*)d_in[1];
    const float* sinp   = (const float*)d_in[2];
    const float* qkv_w  = (const float*)d_in[3];
    const float* qkv_b  = (const float*)d_in[4];
    const float* proj_w = (const float*)d_in[5];
    const float* proj_b = (const float*)d_in[6];
    float* out = (float*)d_out;

    float *qkv_s = nullptr, *ropeT_s = nullptr, *attn_s = nullptr;
    cudaGetSymbolAddress((void**)&qkv_s,   g_qkv);
    cudaGetSymbolAddress((void**)&ropeT_s, g_ropeT);
    cudaGetSymbolAddress((void**)&attn_s,  g_attn);

    const int rope_smem = 3 * 64 * 67 * 4;  // 51456
    cudaFuncSetAttribute(rope_t_kernel,
                         cudaFuncAttributeMaxDynamicSharedMemorySize, rope_smem);
    cudaFuncSetAttribute(flash_kernel,
                         cudaFuncAttributeMaxDynamicSharedMemorySize, FLASH_SMEM_BYTES);

    // 1) QKV GEMM
    gemm_nt_bias<<<dim3(3 * C_ / 128, M_ / 128), 256>>>(
        hidden, qkv_w, qkv_b, qkv_s, 3 * C_, C_);

    // 2) RoPE + transpose (q pre-scaled by D^-0.5)
    rope_t_kernel<<<dim3(S_ / 64, 64, 2), 256, rope_smem>>>(
        qkv_s, cosp, sinp, ropeT_s);

    // 3) Flash attention v3 (BK=64, 2 CTAs/SM)
    flash_kernel<<<dim3(S_ / 128, 64), 256, FLASH_SMEM_BYTES>>>(
        ropeT_s, qkv_s, attn_s);

    // 4) Proj GEMM
    gemm_nt_bias<<<dim3(C_ / 128, M_ / 128), 256>>>(
        attn_s, proj_w, proj_b, out, C_, C_);
}

// round 10
// speedup vs baseline: 1.4023x; 1.1918x over previous
#include <cuda_runtime.h>
#include <cuda_bf16.h>
#include <cstdint>

// ---------------------------------------------------------------------------
// Problem constants: B=4, S=2048, C=1024, H=16, D=64
// ---------------------------------------------------------------------------
#define S_   2048
#define C_   1024
#define H_   16
#define D_   64
#define M_   8192           // B*S rows

// Scratch (static device globals; allocation-free per harness rules)
__device__ float g_qkv[(size_t)M_ * 3 * C_];            // (B,S,3,H,D)
__device__ float g_ropeT[(size_t)64 * 2 * D_ * S_];     // [bh][t][d][s]
__device__ float g_attn[(size_t)M_ * C_];               // (B,S,C)

// bf16 hi/lo split operands for tensor-core GEMMs
__device__ __nv_bfloat16 g_hid_h[(size_t)M_ * C_];
__device__ __nv_bfloat16 g_hid_l[(size_t)M_ * C_];
__device__ __nv_bfloat16 g_qw_h[(size_t)3 * C_ * C_];
__device__ __nv_bfloat16 g_qw_l[(size_t)3 * C_ * C_];
__device__ __nv_bfloat16 g_pw_h[(size_t)C_ * C_];
__device__ __nv_bfloat16 g_pw_l[(size_t)C_ * C_];
__device__ __nv_bfloat16 g_at_h[(size_t)M_ * C_];
__device__ __nv_bfloat16 g_at_l[(size_t)M_ * C_];

// ---------------------------------------------------------------------------
// f32x2 packed helpers (used by flash)
// ---------------------------------------------------------------------------
__device__ __forceinline__ unsigned long long pack2(float lo, float hi) {
    unsigned long long r;
    asm("mov.b64 %0, {%1, %2};" : "=l"(r) : "f"(lo), "f"(hi));
    return r;
}
__device__ __forceinline__ void unpack2(unsigned long long v, float& lo, float& hi) {
    asm("mov.b64 {%0, %1}, %2;" : "=f"(lo), "=f"(hi) : "l"(v));
}
__device__ __forceinline__ unsigned long long ffma2(unsigned long long a,
                                                    unsigned long long b,
                                                    unsigned long long c) {
    unsigned long long d;
    asm("fma.rn.f32x2 %0, %1, %2, %3;" : "=l"(d) : "l"(a), "l"(b), "l"(c));
    return d;
}
__device__ __forceinline__ unsigned long long fmul2(unsigned long long a,
                                                    unsigned long long b) {
    unsigned long long d;
    asm("mul.rn.f32x2 %0, %1, %2;" : "=l"(d) : "l"(a), "l"(b));
    return d;
}

// ---------------------------------------------------------------------------
// Warp-MMA helpers (baseline sm_80+ PTX — no sm_103a-only features)
// ---------------------------------------------------------------------------
__device__ __forceinline__ uint32_t smem_u32(const void* p) {
    uint32_t a;
    asm("{ .reg .u64 t; cvta.to.shared.u64 t, %1; cvt.u32.u64 %0, t; }"
        : "=r"(a) : "l"(p));
    return a;
}
__device__ __forceinline__ void mma_bf16(float* c, const uint32_t* a, const uint32_t* b) {
    asm volatile(
        "mma.sync.aligned.m16n8k16.row.col.f32.bf16.bf16.f32 "
        "{%0,%1,%2,%3}, {%4,%5,%6,%7}, {%8,%9}, {%0,%1,%2,%3};"
        : "+f"(c[0]), "+f"(c[1]), "+f"(c[2]), "+f"(c[3])
        : "r"(a[0]), "r"(a[1]), "r"(a[2]), "r"(a[3]), "r"(b[0]), "r"(b[1]));
}
__device__ __forceinline__ void ldsm4(uint32_t* r, uint32_t addr) {
    asm volatile("ldmatrix.sync.aligned.m8n8.x4.shared.b16 {%0,%1,%2,%3}, [%4];"
                 : "=r"(r[0]), "=r"(r[1]), "=r"(r[2]), "=r"(r[3]) : "r"(addr));
}
#define SMEM_SWZ128(off) ((off) ^ (((off) >> 3) & 0x70))

// ---------------------------------------------------------------------------
// Split fp32 -> bf16 hi/lo
// ---------------------------------------------------------------------------
__global__ __launch_bounds__(256)
void split_bf16_kernel(const float* __restrict__ src,
                       __nv_bfloat16* __restrict__ hi,
                       __nv_bfloat16* __restrict__ lo, int n)
{
    int i = (blockIdx.x * blockDim.x + threadIdx.x) * 4;
    if (i >= n) return;
    float4 v = *(const float4*)(src + i);
    __nv_bfloat16 h0 = __float2bfloat16(v.x);
    __nv_bfloat16 h1 = __float2bfloat16(v.y);
    __nv_bfloat16 h2 = __float2bfloat16(v.z);
    __nv_bfloat16 h3 = __float2bfloat16(v.w);
    __nv_bfloat16 l0 = __float2bfloat16(v.x - __bfloat162float(h0));
    __nv_bfloat16 l1 = __float2bfloat16(v.y - __bfloat162float(h1));
    __nv_bfloat16 l2 = __float2bfloat16(v.z - __bfloat162float(h2));
    __nv_bfloat16 l3 = __float2bfloat16(v.w - __bfloat162float(h3));
    __nv_bfloat162* hp = (__nv_bfloat162*)(hi + i);
    __nv_bfloat162* lp = (__nv_bfloat162*)(lo + i);
    hp[0] = __halves2bfloat162(h0, h1);
    hp[1] = __halves2bfloat162(h2, h3);
    lp[0] = __halves2bfloat162(l0, l1);
    lp[1] = __halves2bfloat162(l2, l3);
}

// ---------------------------------------------------------------------------
// Tensor-core GEMM via warp mma.sync: C[m][n] = sum_k A[m][k]*W[n][k] + bias[n]
// A,W as bf16 hi/lo; split products hh + hl + lh, fp32 accumulators.
// 128x128 tile/CTA, 256 threads, 8 warps of 64x32. K-chunks of 64.
// smem: 4 tiles of 128x64 bf16 (128 B rows, SW128 swizzle) = 64 KB.
// ---------------------------------------------------------------------------
#define OFF_AH 0
#define OFF_AL 16384
#define OFF_BH 32768
#define OFF_BL 49152
#define MMA_SMEM_BYTES 65536

__global__ __launch_bounds__(256)
void mma_gemm_split(const __nv_bfloat16* __restrict__ Ah,
                    const __nv_bfloat16* __restrict__ Al,
                    const __nv_bfloat16* __restrict__ Bh,
                    const __nv_bfloat16* __restrict__ Bl,
                    const float* __restrict__ bias,
                    float* __restrict__ Cout, int N, int K)
{
    extern __shared__ char smem[];
    const uint32_t sb = smem_u32(smem);
    const int tid  = threadIdx.x;
    const int lane = tid & 31;
    const int w    = tid >> 5;
    const int wm   = (w & 1) * 64;        // warp M offset in tile
    const int wn   = (w >> 1) * 32;       // warp N offset in tile
    const int m0 = blockIdx.y * 128;
    const int n0 = blockIdx.x * 128;

    float acc[4][4][4];                    // [mt][nt][c0..c3]
#pragma unroll
    for (int i = 0; i < 4; ++i)
#pragma unroll
        for (int j = 0; j < 4; ++j) {
            acc[i][j][0] = 0.f; acc[i][j][1] = 0.f;
            acc[i][j][2] = 0.f; acc[i][j][3] = 0.f;
        }

    const __nv_bfloat16* aSrcH = Ah + (size_t)m0 * K;
    const __nv_bfloat16* aSrcL = Al + (size_t)m0 * K;
    const __nv_bfloat16* bSrcH = Bh + (size_t)n0 * K;
    const __nv_bfloat16* bSrcL = Bl + (size_t)n0 * K;

    // ldmatrix base offsets (within a 128x64-bf16 tile, bytes, pre-swizzle)
    const uint32_t aoff = (uint32_t)(wm + (lane & 15)) * 128 + (uint32_t)(lane >> 4) * 16;
    const uint32_t boff = (uint32_t)(wn + (lane >> 4) * 8 + (lane & 7)) * 128
                        + (uint32_t)((lane >> 3) & 1) * 16;

    const int nchunks = K >> 6;
    for (int c = 0; c < nchunks; ++c) {
        const int k0 = c << 6;
        __syncthreads();   // previous chunk's MMAs done reading smem
        // stage 4 tiles of 128x64 bf16 (coalesced LDG.128, conflict-free STS.128)
#pragma unroll
        for (int it = 0; it < 4; ++it) {
            int g   = it * 256 + tid;          // 0..1023
            int row = g >> 3;
            int c8  = g & 7;
            uint32_t soff = SMEM_SWZ128((uint32_t)(row * 128 + c8 * 16));
            size_t goff = (size_t)row * K + k0 + c8 * 8;
            *(uint4*)(smem + OFF_AH + soff) = *(const uint4*)(aSrcH + goff);
            *(uint4*)(smem + OFF_AL + soff) = *(const uint4*)(aSrcL + goff);
            *(uint4*)(smem + OFF_BH + soff) = *(const uint4*)(bSrcH + goff);
            *(uint4*)(smem + OFF_BL + soff) = *(const uint4*)(bSrcL + goff);
        }
        __syncthreads();

#pragma unroll
        for (int ks = 0; ks < 4; ++ks) {
            const uint32_t kbyte = (uint32_t)ks * 32;   // k16 step = 32 bytes
            uint32_t aH[4][4], aL[4][4];
#pragma unroll
            for (int mt = 0; mt < 4; ++mt) {
                uint32_t off = SMEM_SWZ128(aoff + (uint32_t)mt * 16 * 128 + kbyte);
                ldsm4(aH[mt], sb + OFF_AH + off);
                ldsm4(aL[mt], sb + OFF_AL + off);
            }
            uint32_t bH[2][4], bL[2][4];                // [pair nt/nt+1]
#pragma unroll
            for (int np = 0; np < 2; ++np) {
                uint32_t off = SMEM_SWZ128(boff + (uint32_t)np * 16 * 128 + kbyte);
                ldsm4(bH[np], sb + OFF_BH + off);
                ldsm4(bL[np], sb + OFF_BL + off);
            }
#pragma unroll
            for (int mt = 0; mt < 4; ++mt)
#pragma unroll
                for (int nt = 0; nt < 4; ++nt) {
                    const uint32_t* bh = &bH[nt >> 1][(nt & 1) * 2];
                    const uint32_t* bl = &bL[nt >> 1][(nt & 1) * 2];
                    mma_bf16(acc[mt][nt], aH[mt], bh);
                    mma_bf16(acc[mt][nt], aH[mt], bl);
                    mma_bf16(acc[mt][nt], aL[mt], bh);
                }
        }
    }

    // ---- epilogue: fragment-direct stores + bias ----
    const int gq = lane >> 2;
    const int tq = lane & 3;
#pragma unroll
    for (int nt = 0; nt < 4; ++nt) {
        float2 bb = *(const float2*)&bias[n0 + wn + nt * 8 + tq * 2];
#pragma unroll
        for (int mt = 0; mt < 4; ++mt) {
            int r0 = m0 + wm + mt * 16 + gq;
            int col = n0 + wn + nt * 8 + tq * 2;
            float2 v0 = make_float2(acc[mt][nt][0] + bb.x, acc[mt][nt][1] + bb.y);
            float2 v1 = make_float2(acc[mt][nt][2] + bb.x, acc[mt][nt][3] + bb.y);
            *(float2*)&Cout[(size_t)r0 * N + col]       = v0;
            *(float2*)&Cout[(size_t)(r0 + 8) * N + col] = v1;
        }
    }
}

// ---------------------------------------------------------------------------
// RoPE + transpose. q (t=0) pre-scaled by D^-0.5 = 0.125.   (unchanged)
// ---------------------------------------------------------------------------
__global__ __launch_bounds__(256)
void rope_t_kernel(const float* __restrict__ qkv,
                   const float* __restrict__ cosp,
                   const float* __restrict__ sinp,
                   float* __restrict__ ropeT)
{
    extern __shared__ float rs[];
    float* Tx = rs;
    float* Tc = rs + 64 * 67;
    float* Ts = rs + 2 * 64 * 67;

    const int tid = threadIdx.x;
    const int s0  = blockIdx.x * 64;
    const int bh  = blockIdx.y;
    const int b   = bh >> 4;
    const int h   = bh & 15;
    const int t   = blockIdx.z;
    const float qs = (t == 0) ? 0.125f : 1.0f;

#pragma unroll
    for (int it = 0; it < 4; ++it) {
        int idx = it * 256 + tid;
        int sl  = idx >> 4;
        int dc  = (idx & 15) * 4;
        size_t bs = (size_t)(b * S_ + s0 + sl);
        float4 xv = *(const float4*)(qkv + (bs * 3 + t) * C_ + h * D_ + dc);
        float4 cv = *(const float4*)(cosp + bs * D_ + dc);
        float4 sv = *(const float4*)(sinp + bs * D_ + dc);
        Tx[sl * 67 + dc + 0] = xv.x; Tx[sl * 67 + dc + 1] = xv.y;
        Tx[sl * 67 + dc + 2] = xv.z; Tx[sl * 67 + dc + 3] = xv.w;
        Tc[sl * 67 + dc + 0] = cv.x; Tc[sl * 67 + dc + 1] = cv.y;
        Tc[sl * 67 + dc + 2] = cv.z; Tc[sl * 67 + dc + 3] = cv.w;
        Ts[sl * 67 + dc + 0] = sv.x; Ts[sl * 67 + dc + 1] = sv.y;
        Ts[sl * 67 + dc + 2] = sv.z; Ts[sl * 67 + dc + 3] = sv.w;
    }
    __syncthreads();

#pragma unroll
    for (int it = 0; it < 4; ++it) {
        int idx = it * 256 + tid;
        int d   = idx >> 4;
        int sc  = (idx & 15) * 4;
        float out[4];
#pragma unroll
        for (int j = 0; j < 4; ++j) {
            int sl = sc + j;
            float x0 = Tx[sl * 67 + d];
            float x1 = Tx[sl * 67 + (d ^ 32)];
            float c  = Tc[sl * 67 + d];
            float sn = Ts[sl * 67 + d];
            float rh = (d < 32) ? -x1 : x1;
            out[j] = qs * fmaf(x0, c, rh * sn);
        }
        *(float4*)(ropeT + ((size_t)(bh * 2 + t) * D_ + d) * S_ + s0 + sc) =
            make_float4(out[0], out[1], out[2], out[3]);
    }
}

// ---------------------------------------------------------------------------
// Flash attention v3 (unchanged): BQ=128, BK=64, 256 thr, 2 CTAs/SM.
// ---------------------------------------------------------------------------
#define FLASH_SMEM_FLOATS (64*132 + 64*68 + 64*68 + 128*68)
#define FLASH_SMEM_BYTES  (FLASH_SMEM_FLOATS * 4)   // 103,424 B

__global__ __launch_bounds__(256, 2)
void flash_kernel(const float* __restrict__ ropeT,
                  const float* __restrict__ qkv,
                  float* __restrict__ attn)
{
    extern __shared__ float sm[];
    float* QT = sm;                           // [64][132]
    float* KT = sm + 64 * 132;                // [64][68]
    float* Vs = sm + 64 * 132 + 64 * 68;      // [64][68]
    float* Ps = sm + 64 * 132 + 2 * 64 * 68;  // [128][68]

    const int tid = threadIdx.x;
    const int cx  = tid & 7;
    const int ry  = tid >> 3;
    const int qb  = blockIdx.x;
    const int bh  = blockIdx.y;
    const int b   = bh >> 4;
    const int h   = bh & 15;
    const int q0  = qb * 128;

    const float* qsrc = ropeT + (size_t)(bh * 2 + 0) * D_ * S_;
#pragma unroll
    for (int it = 0; it < 8; ++it) {
        int idx = it * 256 + tid;
        int d   = idx >> 5;
        int sc  = (idx & 31) * 4;
        float4 v = *(const float4*)(qsrc + (size_t)d * S_ + q0 + sc);
        *(float4*)&QT[d * 132 + sc] = v;
    }

    float m_i[4], l_i[4];
    unsigned long long o[4][4];
#pragma unroll
    for (int i = 0; i < 4; ++i) {
        m_i[i] = -1.0e30f; l_i[i] = 0.0f;
        o[i][0] = 0ull; o[i][1] = 0ull; o[i][2] = 0ull; o[i][3] = 0ull;
    }

    const float* ksrc = ropeT + (size_t)(bh * 2 + 1) * D_ * S_;

    for (int kb = 0; kb < 32; ++kb) {
        __syncthreads();
        const int k0 = kb * 64;
#pragma unroll
        for (int it = 0; it < 4; ++it) {
            int idx = it * 256 + tid;
            int d   = idx >> 4;
            int sc  = (idx & 15) * 4;
            float4 v = *(const float4*)(ksrc + (size_t)d * S_ + k0 + sc);
            *(float4*)&KT[d * 68 + sc] = v;
        }
#pragma unroll
        for (int it = 0; it < 4; ++it) {
            int idx = it * 256 + tid;
            int sl  = idx >> 4;
            int dc  = (idx & 15) * 4;
            float4 v = *(const float4*)(qkv +
                ((size_t)(b * S_ + k0 + sl) * 3 + 2) * C_ + h * D_ + dc);
            *(float4*)&Vs[sl * 68 + dc] = v;
        }
        __syncthreads();

        unsigned long long acc[4][4];
#pragma unroll
        for (int i = 0; i < 4; ++i) {
            acc[i][0] = 0ull; acc[i][1] = 0ull;
            acc[i][2] = 0ull; acc[i][3] = 0ull;
        }
#pragma unroll 4
        for (int d = 0; d < 64; ++d) {
            float4 qv = *(const float4*)&QT[d * 132 + ry * 4];
            ulonglong2 ka = *(const ulonglong2*)&KT[d * 68 + cx * 4];
            ulonglong2 kc = *(const ulonglong2*)&KT[d * 68 + 32 + cx * 4];
            float qarr[4] = {qv.x, qv.y, qv.z, qv.w};
#pragma unroll
            for (int i = 0; i < 4; ++i) {
                unsigned long long qq = pack2(qarr[i], qarr[i]);
                acc[i][0] = ffma2(qq, ka.x, acc[i][0]);
                acc[i][1] = ffma2(qq, ka.y, acc[i][1]);
                acc[i][2] = ffma2(qq, kc.x, acc[i][2]);
                acc[i][3] = ffma2(qq, kc.y, acc[i][3]);
            }
        }

#pragma unroll
        for (int i = 0; i < 4; ++i) {
            float s0, s1, s2, s3, s4, s5, s6, s7;
            unpack2(acc[i][0], s0, s1);
            unpack2(acc[i][1], s2, s3);
            unpack2(acc[i][2], s4, s5);
            unpack2(acc[i][3], s6, s7);
            float mx = fmaxf(fmaxf(fmaxf(s0, s1), fmaxf(s2, s3)),
                             fmaxf(fmaxf(s4, s5), fmaxf(s6, s7)));
#pragma unroll
            for (int off = 1; off < 8; off <<= 1)
                mx = fmaxf(mx, __shfl_xor_sync(0xffffffffu, mx, off));
            float mnew  = fmaxf(m_i[i], mx);
            float alpha = __expf(m_i[i] - mnew);
            m_i[i] = mnew;
            float p0 = __expf(s0 - mnew), p1 = __expf(s1 - mnew);
            float p2 = __expf(s2 - mnew), p3 = __expf(s3 - mnew);
            float p4 = __expf(s4 - mnew), p5 = __expf(s5 - mnew);
            float p6 = __expf(s6 - mnew), p7 = __expf(s7 - mnew);
            float lsum = ((p0 + p1) + (p2 + p3)) + ((p4 + p5) + (p6 + p7));
#pragma unroll
            for (int off = 1; off < 8; off <<= 1)
                lsum += __shfl_xor_sync(0xffffffffu, lsum, off);
            l_i[i] = l_i[i] * alpha + lsum;
            unsigned long long a2 = pack2(alpha, alpha);
            o[i][0] = fmul2(o[i][0], a2);
            o[i][1] = fmul2(o[i][1], a2);
            o[i][2] = fmul2(o[i][2], a2);
            o[i][3] = fmul2(o[i][3], a2);
            int r = ry * 4 + i;
            *(float4*)&Ps[r * 68 + cx * 4]      = make_float4(p0, p1, p2, p3);
            *(float4*)&Ps[r * 68 + 32 + cx * 4] = make_float4(p4, p5, p6, p7);
        }
        __syncthreads();

#pragma unroll 2
        for (int kc = 0; kc < 64; kc += 4) {
            ulonglong2 va[4], vb[4];
#pragma unroll
            for (int k = 0; k < 4; ++k) {
                va[k] = *(const ulonglong2*)&Vs[(kc + k) * 68 + cx * 4];
                vb[k] = *(const ulonglong2*)&Vs[(kc + k) * 68 + 32 + cx * 4];
            }
#pragma unroll
            for (int i = 0; i < 4; ++i) {
                float4 pf = *(const float4*)&Ps[(ry * 4 + i) * 68 + kc];
                unsigned long long pd0 = pack2(pf.x, pf.x);
                unsigned long long pd1 = pack2(pf.y, pf.y);
                unsigned long long pd2 = pack2(pf.z, pf.z);
                unsigned long long pd3 = pack2(pf.w, pf.w);
                o[i][0] = ffma2(pd0, va[0].x, o[i][0]);
                o[i][1] = ffma2(pd0, va[0].y, o[i][1]);
                o[i][2] = ffma2(pd0, vb[0].x, o[i][2]);
                o[i][3] = ffma2(pd0, vb[0].y, o[i][3]);
                o[i][0] = ffma2(pd1, va[1].x, o[i][0]);
                o[i][1] = ffma2(pd1, va[1].y, o[i][1]);
                o[i][2] = ffma2(pd1, vb[1].x, o[i][2]);
                o[i][3] = ffma2(pd1, vb[1].y, o[i][3]);
                o[i][0] = ffma2(pd2, va[2].x, o[i][0]);
                o[i][1] = ffma2(pd2, va[2].y, o[i][1]);
                o[i][2] = ffma2(pd2, vb[2].x, o[i][2]);
                o[i][3] = ffma2(pd2, vb[2].y, o[i][3]);
                o[i][0] = ffma2(pd3, va[3].x, o[i][0]);
                o[i][1] = ffma2(pd3, va[3].y, o[i][1]);
                o[i][2] = ffma2(pd3, vb[3].x, o[i][2]);
                o[i][3] = ffma2(pd3, vb[3].y, o[i][3]);
            }
        }
    }

#pragma unroll
    for (int i = 0; i < 4; ++i) {
        float inv = 1.0f / l_i[i];
        float o0, o1, o2, o3, o4, o5, o6, o7;
        unpack2(o[i][0], o0, o1);
        unpack2(o[i][1], o2, o3);
        unpack2(o[i][2], o4, o5);
        unpack2(o[i][3], o6, o7);
        size_t row = (size_t)(b * S_ + q0 + ry * 4 + i);
        float* op = attn + row * C_ + h * D_;
        *(float4*)(op + cx * 4) =
            make_float4(o0 * inv, o1 * inv, o2 * inv, o3 * inv);
        *(float4*)(op + 32 + cx * 4) =
            make_float4(o4 * inv, o5 * inv, o6 * inv, o7 * inv);
    }
}

// ---------------------------------------------------------------------------
// Launch
// ---------------------------------------------------------------------------
extern "C" void kernel_launch(void* const* d_in, const int* in_sizes, int n_in,
                              void* d_out, int out_size)
{
    (void)in_sizes; (void)n_in; (void)out_size;
    const float* hidden = (const float*)d_in[0];
    const float* cosp   = (const float*)d_in[1];
    const float* sinp   = (const float*)d_in[2];
    const float* qkv_w  = (const float*)d_in[3];
    const float* qkv_b  = (const float*)d_in[4];
    const float* proj_w = (const float*)d_in[5];
    const float* proj_b = (const float*)d_in[6];
    float* out = (float*)d_out;

    float *qkv_s, *ropeT_s, *attn_s;
    __nv_bfloat16 *hidH, *hidL, *qwH, *qwL, *pwH, *pwL, *atH, *atL;
    cudaGetSymbolAddress((void**)&qkv_s,   g_qkv);
    cudaGetSymbolAddress((void**)&ropeT_s, g_ropeT);
    cudaGetSymbolAddress((void**)&attn_s,  g_attn);
    cudaGetSymbolAddress((void**)&hidH, g_hid_h);
    cudaGetSymbolAddress((void**)&hidL, g_hid_l);
    cudaGetSymbolAddress((void**)&qwH,  g_qw_h);
    cudaGetSymbolAddress((void**)&qwL,  g_qw_l);
    cudaGetSymbolAddress((void**)&pwH,  g_pw_h);
    cudaGetSymbolAddress((void**)&pwL,  g_pw_l);
    cudaGetSymbolAddress((void**)&atH,  g_at_h);
    cudaGetSymbolAddress((void**)&atL,  g_at_l);

    const int rope_smem = 3 * 64 * 67 * 4;
    cudaFuncSetAttribute(rope_t_kernel,
                         cudaFuncAttributeMaxDynamicSharedMemorySize, rope_smem);
    cudaFuncSetAttribute(flash_kernel,
                         cudaFuncAttributeMaxDynamicSharedMemorySize, FLASH_SMEM_BYTES);
    cudaFuncSetAttribute(mma_gemm_split,
                         cudaFuncAttributeMaxDynamicSharedMemorySize, MMA_SMEM_BYTES);

    // 0) split inputs / weights to bf16 hi+lo
    split_bf16_kernel<<<(M_ * C_ / 4 + 255) / 256, 256>>>(hidden, hidH, hidL, M_ * C_);
    split_bf16_kernel<<<(3 * C_ * C_ / 4 + 255) / 256, 256>>>(qkv_w, qwH, qwL, 3 * C_ * C_);
    split_bf16_kernel<<<(C_ * C_ / 4 + 255) / 256, 256>>>(proj_w, pwH, pwL, C_ * C_);

    // 1) QKV GEMM on tensor cores (warp mma.sync)
    mma_gemm_split<<<dim3(3 * C_ / 128, M_ / 128), 256, MMA_SMEM_BYTES>>>(
        hidH, hidL, qwH, qwL, qkv_b, qkv_s, 3 * C_, C_);

    // 2) RoPE + transpose (q pre-scaled by D^-0.5)
    rope_t_kernel<<<dim3(S_ / 64, 64, 2), 256, rope_smem>>>(
        qkv_s, cosp, sinp, ropeT_s);

    // 3) Flash attention (fp32, unchanged)
    flash_kernel<<<dim3(S_ / 128, 64), 256, FLASH_SMEM_BYTES>>>(
        ropeT_s, qkv_s, attn_s);

    // 4) split attn, proj GEMM on tensor cores
    split_bf16_kernel<<<(M_ * C_ / 4 + 255) / 256, 256>>>(attn_s, atH, atL, M_ * C_);
    mma_gemm_split<<<dim3(C_ / 128, M_ / 128), 256, MMA_SMEM_BYTES>>>(
        atH, atL, pwH, pwL, proj_b, out, C_, C_);
}

// round 11
// speedup vs baseline: 2.9085x; 2.0740x over previous
#include <cuda_runtime.h>
#include <cuda_bf16.h>
#include <cstdint>

// ---------------------------------------------------------------------------
// Problem constants: B=4, S=2048, C=1024, H=16, D=64
// ---------------------------------------------------------------------------
#define S_   2048
#define C_   1024
#define H_   16
#define D_   64
#define M_   8192           // B*S rows

// Scratch (static device globals; allocation-free per harness rules)
__device__ float g_qkv[(size_t)M_ * 3 * C_];            // (B,S,3,H,D) fp32
__device__ float g_attn[(size_t)M_ * C_];               // (B,S,C) fp32

// bf16 hi/lo split operands for tensor-core GEMMs
__device__ __nv_bfloat16 g_hid_h[(size_t)M_ * C_];
__device__ __nv_bfloat16 g_hid_l[(size_t)M_ * C_];
__device__ __nv_bfloat16 g_qw_h[(size_t)3 * C_ * C_];
__device__ __nv_bfloat16 g_qw_l[(size_t)3 * C_ * C_];
__device__ __nv_bfloat16 g_pw_h[(size_t)C_ * C_];
__device__ __nv_bfloat16 g_pw_l[(size_t)C_ * C_];
__device__ __nv_bfloat16 g_at_h[(size_t)M_ * C_];
__device__ __nv_bfloat16 g_at_l[(size_t)M_ * C_];

// bf16 hi/lo q/k/v for flash, row-major [bh][s][64]
__device__ __nv_bfloat16 g_fqh[(size_t)64 * S_ * D_];
__device__ __nv_bfloat16 g_fql[(size_t)64 * S_ * D_];
__device__ __nv_bfloat16 g_fkh[(size_t)64 * S_ * D_];
__device__ __nv_bfloat16 g_fkl[(size_t)64 * S_ * D_];
__device__ __nv_bfloat16 g_fvh[(size_t)64 * S_ * D_];
__device__ __nv_bfloat16 g_fvl[(size_t)64 * S_ * D_];

// ---------------------------------------------------------------------------
// PTX helpers (all baseline sm_80+ — compile for plain sm_103 target)
// ---------------------------------------------------------------------------
__device__ __forceinline__ uint32_t smem_u32(const void* p) {
    uint32_t a;
    asm("{ .reg .u64 t; cvta.to.shared.u64 t, %1; cvt.u32.u64 %0, t; }"
        : "=r"(a) : "l"(p));
    return a;
}
__device__ __forceinline__ void mma_bf16(float* c, const uint32_t* a, const uint32_t* b) {
    asm volatile(
        "mma.sync.aligned.m16n8k16.row.col.f32.bf16.bf16.f32 "
        "{%0,%1,%2,%3}, {%4,%5,%6,%7}, {%8,%9}, {%0,%1,%2,%3};"
        : "+f"(c[0]), "+f"(c[1]), "+f"(c[2]), "+f"(c[3])
        : "r"(a[0]), "r"(a[1]), "r"(a[2]), "r"(a[3]), "r"(b[0]), "r"(b[1]));
}
__device__ __forceinline__ void ldsm4(uint32_t* r, uint32_t addr) {
    asm volatile("ldmatrix.sync.aligned.m8n8.x4.shared.b16 {%0,%1,%2,%3}, [%4];"
                 : "=r"(r[0]), "=r"(r[1]), "=r"(r[2]), "=r"(r[3]) : "r"(addr));
}
__device__ __forceinline__ void ldsm4t(uint32_t* r, uint32_t addr) {
    asm volatile("ldmatrix.sync.aligned.m8n8.x4.trans.shared.b16 {%0,%1,%2,%3}, [%4];"
                 : "=r"(r[0]), "=r"(r[1]), "=r"(r[2]), "=r"(r[3]) : "r"(addr));
}
#define SMEM_SWZ128(off) ((off) ^ (((off) >> 3) & 0x70))
#define CP16(dst, src) \
    asm volatile("cp.async.ca.shared.global [%0], [%1], 16;" \
                 :: "r"(dst), "l"(__cvta_generic_to_global(src)))
#define CP_COMMIT() asm volatile("cp.async.commit_group;" ::: "memory")
#define CP_WAIT0()  asm volatile("cp.async.wait_group 0;" ::: "memory")

__device__ __forceinline__ uint32_t pack_bf16x2(__nv_bfloat16 lo, __nv_bfloat16 hi) {
    __nv_bfloat162 t = __halves2bfloat162(lo, hi);
    return *(uint32_t*)&t;
}

// ---------------------------------------------------------------------------
// Split fp32 -> bf16 hi/lo
// ---------------------------------------------------------------------------
__global__ __launch_bounds__(256)
void split_bf16_kernel(const float* __restrict__ src,
                       __nv_bfloat16* __restrict__ hi,
                       __nv_bfloat16* __restrict__ lo, int n)
{
    int i = (blockIdx.x * blockDim.x + threadIdx.x) * 4;
    if (i >= n) return;
    float4 v = *(const float4*)(src + i);
    __nv_bfloat16 h0 = __float2bfloat16(v.x);
    __nv_bfloat16 h1 = __float2bfloat16(v.y);
    __nv_bfloat16 h2 = __float2bfloat16(v.z);
    __nv_bfloat16 h3 = __float2bfloat16(v.w);
    __nv_bfloat16 l0 = __float2bfloat16(v.x - __bfloat162float(h0));
    __nv_bfloat16 l1 = __float2bfloat16(v.y - __bfloat162float(h1));
    __nv_bfloat16 l2 = __float2bfloat16(v.z - __bfloat162float(h2));
    __nv_bfloat16 l3 = __float2bfloat16(v.w - __bfloat162float(h3));
    __nv_bfloat162* hp = (__nv_bfloat162*)(hi + i);
    __nv_bfloat162* lp = (__nv_bfloat162*)(lo + i);
    hp[0] = __halves2bfloat162(h0, h1);
    hp[1] = __halves2bfloat162(h2, h3);
    lp[0] = __halves2bfloat162(l0, l1);
    lp[1] = __halves2bfloat162(l2, l3);
}

// ---------------------------------------------------------------------------
// Tensor-core GEMM (mma.sync, hi/lo split, cp.async DOUBLE-BUFFERED).
// C[m][n] = sum_k A[m][k]*W[n][k] + bias[n]. 128x128 tile, 256 thr, 8 warps.
// ---------------------------------------------------------------------------
#define OFF_AH 0
#define OFF_AL 16384
#define OFF_BH 32768
#define OFF_BL 49152
#define MMA_SMEM_BYTES 131072     // 2 x 64 KB buffers

#define GEMM_STAGE(cc, pp) do {                                              \
    int k0s = (cc) << 6;                                                     \
    uint32_t base_ = sb + (uint32_t)(pp) * 65536u;                           \
    char* bptr_ = smem + (size_t)(pp) * 65536u;                              \
    (void)base_;                                                             \
    _Pragma("unroll")                                                        \
    for (int it = 0; it < 4; ++it) {                                         \
        int g   = it * 256 + tid;                                            \
        int row = g >> 3;                                                    \
        int c8  = g & 7;                                                     \
        uint32_t soff = SMEM_SWZ128((uint32_t)(row * 128 + c8 * 16));        \
        size_t goff = (size_t)row * K + k0s + c8 * 8;                        \
        uint32_t db = smem_u32(bptr_);                                       \
        CP16(db + OFF_AH + soff, aSrcH + goff);                              \
        CP16(db + OFF_AL + soff, aSrcL + goff);                              \
        CP16(db + OFF_BH + soff, bSrcH + goff);                              \
        CP16(db + OFF_BL + soff, bSrcL + goff);                              \
    }                                                                        \
} while (0)

__global__ __launch_bounds__(256)
void mma_gemm_split(const __nv_bfloat16* __restrict__ Ah,
                    const __nv_bfloat16* __restrict__ Al,
                    const __nv_bfloat16* __restrict__ Bh,
                    const __nv_bfloat16* __restrict__ Bl,
                    const float* __restrict__ bias,
                    float* __restrict__ Cout, int N, int K)
{
    extern __shared__ char smem[];
    const uint32_t sb = smem_u32(smem);
    const int tid  = threadIdx.x;
    const int lane = tid & 31;
    const int w    = tid >> 5;
    const int wm   = (w & 1) * 64;
    const int wn   = (w >> 1) * 32;
    const int m0 = blockIdx.y * 128;
    const int n0 = blockIdx.x * 128;

    float acc[4][4][4];
#pragma unroll
    for (int i = 0; i < 4; ++i)
#pragma unroll
        for (int j = 0; j < 4; ++j) {
            acc[i][j][0] = 0.f; acc[i][j][1] = 0.f;
            acc[i][j][2] = 0.f; acc[i][j][3] = 0.f;
        }

    const __nv_bfloat16* aSrcH = Ah + (size_t)m0 * K;
    const __nv_bfloat16* aSrcL = Al + (size_t)m0 * K;
    const __nv_bfloat16* bSrcH = Bh + (size_t)n0 * K;
    const __nv_bfloat16* bSrcL = Bl + (size_t)n0 * K;

    const uint32_t aoff = (uint32_t)(wm + (lane & 15)) * 128 + (uint32_t)(lane >> 4) * 16;
    const uint32_t boff = (uint32_t)(wn + (lane >> 4) * 8 + (lane & 7)) * 128
                        + (uint32_t)((lane >> 3) & 1) * 16;

    const int nchunks = K >> 6;
    GEMM_STAGE(0, 0); CP_COMMIT();

    for (int c = 0; c < nchunks; ++c) {
        CP_WAIT0();
        __syncthreads();
        if (c + 1 < nchunks) { GEMM_STAGE(c + 1, (c + 1) & 1); CP_COMMIT(); }
        const uint32_t tb = sb + (uint32_t)(c & 1) * 65536u;

#pragma unroll
        for (int ks = 0; ks < 4; ++ks) {
            const uint32_t kbyte = (uint32_t)ks * 32;
            uint32_t aH[4][4], aL[4][4];
#pragma unroll
            for (int mt = 0; mt < 4; ++mt) {
                uint32_t off = SMEM_SWZ128(aoff + (uint32_t)mt * 16 * 128 + kbyte);
                ldsm4(aH[mt], tb + OFF_AH + off);
                ldsm4(aL[mt], tb + OFF_AL + off);
            }
            uint32_t bH[2][4], bL[2][4];
#pragma unroll
            for (int np = 0; np < 2; ++np) {
                uint32_t off = SMEM_SWZ128(boff + (uint32_t)np * 16 * 128 + kbyte);
                ldsm4(bH[np], tb + OFF_BH + off);
                ldsm4(bL[np], tb + OFF_BL + off);
            }
#pragma unroll
            for (int mt = 0; mt < 4; ++mt)
#pragma unroll
                for (int nt = 0; nt < 4; ++nt) {
                    const uint32_t* bh = &bH[nt >> 1][(nt & 1) * 2];
                    const uint32_t* bl = &bL[nt >> 1][(nt & 1) * 2];
                    mma_bf16(acc[mt][nt], aH[mt], bh);
                    mma_bf16(acc[mt][nt], aH[mt], bl);
                    mma_bf16(acc[mt][nt], aL[mt], bh);
                }
        }
    }

    const int gq = lane >> 2;
    const int tq = lane & 3;
#pragma unroll
    for (int nt = 0; nt < 4; ++nt) {
        float2 bb = *(const float2*)&bias[n0 + wn + nt * 8 + tq * 2];
#pragma unroll
        for (int mt = 0; mt < 4; ++mt) {
            int r0 = m0 + wm + mt * 16 + gq;
            int col = n0 + wn + nt * 8 + tq * 2;
            float2 v0 = make_float2(acc[mt][nt][0] + bb.x, acc[mt][nt][1] + bb.y);
            float2 v1 = make_float2(acc[mt][nt][2] + bb.x, acc[mt][nt][3] + bb.y);
            *(float2*)&Cout[(size_t)r0 * N + col]       = v0;
            *(float2*)&Cout[(size_t)(r0 + 8) * N + col] = v1;
        }
    }
}

// ---------------------------------------------------------------------------
// RoPE + hi/lo split of q,k,v into bf16 row-major [bh][s][64].
// q (t=0) gets rope + 0.125 scale; k (t=1) rope; v (t=2) passthrough.
// grid (B*S, 3), 256 threads: thread = (head = tid>>4, dgroup = (tid&15)*4).
// ---------------------------------------------------------------------------
__global__ __launch_bounds__(256)
void rope_split_kernel(const float* __restrict__ qkv,
                       const float* __restrict__ cosp,
                       const float* __restrict__ sinp,
                       __nv_bfloat16* __restrict__ qh, __nv_bfloat16* __restrict__ ql,
                       __nv_bfloat16* __restrict__ kh, __nv_bfloat16* __restrict__ kl,
                       __nv_bfloat16* __restrict__ vh, __nv_bfloat16* __restrict__ vl)
{
    const int tid = threadIdx.x;
    const int bs  = blockIdx.x;            // 0..8191
    const int t   = blockIdx.y;            // 0..2
    const int hh  = tid >> 4;
    const int dg  = (tid & 15) * 4;

    const float* src = qkv + ((size_t)bs * 3 + t) * C_ + hh * D_;
    float4 x = *(const float4*)(src + dg);
    float out[4];
    if (t < 2) {
        float4 xp = *(const float4*)(src + (dg ^ 32));
        float4 cv = *(const float4*)(cosp + (size_t)bs * D_ + dg);
        float4 sv = *(const float4*)(sinp + (size_t)bs * D_ + dg);
        float sgn = (dg < 32) ? -1.0f : 1.0f;
        out[0] = fmaf(x.x, cv.x, sgn * xp.x * sv.x);
        out[1] = fmaf(x.y, cv.y, sgn * xp.y * sv.y);
        out[2] = fmaf(x.z, cv.z, sgn * xp.z * sv.z);
        out[3] = fmaf(x.w, cv.w, sgn * xp.w * sv.w);
        if (t == 0) { out[0] *= 0.125f; out[1] *= 0.125f; out[2] *= 0.125f; out[3] *= 0.125f; }
    } else {
        out[0] = x.x; out[1] = x.y; out[2] = x.z; out[3] = x.w;
    }

    __nv_bfloat16 *dh, *dl;
    if (t == 0)      { dh = qh; dl = ql; }
    else if (t == 1) { dh = kh; dl = kl; }
    else             { dh = vh; dl = vl; }

    const int b = bs >> 11;
    const int s = bs & 2047;
    size_t di = ((size_t)(b * 16 + hh) * S_ + s) * D_ + dg;

    __nv_bfloat16 h0 = __float2bfloat16(out[0]);
    __nv_bfloat16 h1 = __float2bfloat16(out[1]);
    __nv_bfloat16 h2 = __float2bfloat16(out[2]);
    __nv_bfloat16 h3 = __float2bfloat16(out[3]);
    uint2 hv, lv;
    hv.x = pack_bf16x2(h0, h1);
    hv.y = pack_bf16x2(h2, h3);
    lv.x = pack_bf16x2(__float2bfloat16(out[0] - __bfloat162float(h0)),
                       __float2bfloat16(out[1] - __bfloat162float(h1)));
    lv.y = pack_bf16x2(__float2bfloat16(out[2] - __bfloat162float(h2)),
                       __float2bfloat16(out[3] - __bfloat162float(h3)));
    *(uint2*)(dh + di) = hv;
    *(uint2*)(dl + di) = lv;
}

// ---------------------------------------------------------------------------
// Flash attention v4 — mma.sync bf16 hi/lo split, cp.async double-buffered.
// Grid (S/128, 64bh), 256 threads, 8 warps; warp owns 16 q-rows x all keys.
// smem 64 KB: 2 bufs x {Kh,Kl,Vh,Vl} 64x64 bf16 tiles (8 KB each).
// Q fragments hoisted into registers. S-frags convert to PV A-frags in regs.
// ---------------------------------------------------------------------------
#define FL_SMEM_BYTES 65536

#define FL_STAGEKV(kbv, pp) do {                                             \
    uint32_t base_ = sb + (uint32_t)(pp) * 32768u;                           \
    _Pragma("unroll")                                                        \
    for (int it = 0; it < 2; ++it) {                                         \
        int g   = it * 256 + tid;                                            \
        int row = g >> 3;                                                    \
        int c8  = g & 7;                                                     \
        uint32_t soff = SMEM_SWZ128((uint32_t)(row * 128 + c8 * 16));        \
        size_t go = ((size_t)(kbv) * 64 + row) * 64 + c8 * 8;                \
        CP16(base_ +         soff, khp + go);                                \
        CP16(base_ +  8192 + soff, klp + go);                                \
        CP16(base_ + 16384 + soff, vhp + go);                                \
        CP16(base_ + 24576 + soff, vlp + go);                                \
    }                                                                        \
} while (0)

__global__ __launch_bounds__(256, 1)
void flash_mma_kernel(const __nv_bfloat16* __restrict__ qh,
                      const __nv_bfloat16* __restrict__ ql,
                      const __nv_bfloat16* __restrict__ kh,
                      const __nv_bfloat16* __restrict__ kl,
                      const __nv_bfloat16* __restrict__ vh,
                      const __nv_bfloat16* __restrict__ vl,
                      float* __restrict__ attn)
{
    extern __shared__ char smem[];
    const uint32_t sb = smem_u32(smem);
    const int tid  = threadIdx.x;
    const int lane = tid & 31;
    const int wid  = tid >> 5;
    const int wm   = wid * 16;            // warp's q-row base within tile
    const int qb   = blockIdx.x;
    const int bhid = blockIdx.y;
    const int b    = bhid >> 4;
    const int hd   = bhid & 15;
    const int q0   = qb * 128;

    const __nv_bfloat16* qhp = qh + ((size_t)bhid * S_ + q0) * D_;
    const __nv_bfloat16* qlp = ql + ((size_t)bhid * S_ + q0) * D_;
    const __nv_bfloat16* khp = kh + (size_t)bhid * S_ * D_;
    const __nv_bfloat16* klp = kl + (size_t)bhid * S_ * D_;
    const __nv_bfloat16* vhp = vh + (size_t)bhid * S_ * D_;
    const __nv_bfloat16* vlp = vl + (size_t)bhid * S_ * D_;

    // ---- stage Q (128x64 hi + lo) into smem bytes [0,32K), extract frags ----
#pragma unroll
    for (int it = 0; it < 4; ++it) {
        int g   = it * 256 + tid;
        int row = g >> 3;
        int c8  = g & 7;
        uint32_t soff = SMEM_SWZ128((uint32_t)(row * 128 + c8 * 16));
        CP16(sb +         soff, qhp + (size_t)row * 64 + c8 * 8);
        CP16(sb + 16384 + soff, qlp + (size_t)row * 64 + c8 * 8);
    }
    CP_COMMIT(); CP_WAIT0(); __syncthreads();

    uint32_t qfh[4][4], qfl[4][4];
#pragma unroll
    for (int ks = 0; ks < 4; ++ks) {
        uint32_t off = SMEM_SWZ128((uint32_t)((wm + (lane & 15)) * 128
                                   + (lane >> 4) * 16 + ks * 32));
        ldsm4(qfh[ks], sb + off);
        ldsm4(qfl[ks], sb + 16384 + off);
    }
    __syncthreads();     // all warps done reading Q region before K/V overwrite

    float o[8][4];
#pragma unroll
    for (int i = 0; i < 8; ++i) { o[i][0]=0.f; o[i][1]=0.f; o[i][2]=0.f; o[i][3]=0.f; }
    float m0 = -1.0e30f, m1 = -1.0e30f, l0 = 0.f, l1 = 0.f;

    FL_STAGEKV(0, 0); CP_COMMIT();

    for (int kb = 0; kb < 32; ++kb) {
        const int p = kb & 1;
        CP_WAIT0();
        __syncthreads();
        if (kb + 1 < 32) { FL_STAGEKV(kb + 1, p ^ 1); CP_COMMIT(); }
        const uint32_t kbh = sb + (uint32_t)p * 32768u;
        const uint32_t kbl = kbh + 8192u;
        const uint32_t vbh = kbh + 16384u;
        const uint32_t vbl = kbh + 24576u;

        // ---- S = Q K^T (16 rows x 64 keys per warp, 3-way split) ----
        float s[8][4];
#pragma unroll
        for (int i = 0; i < 8; ++i) { s[i][0]=0.f; s[i][1]=0.f; s[i][2]=0.f; s[i][3]=0.f; }
#pragma unroll
        for (int ks = 0; ks < 4; ++ks) {
            uint32_t fh[4][4], fl[4][4];
#pragma unroll
            for (int ng = 0; ng < 4; ++ng) {
                uint32_t off = SMEM_SWZ128((uint32_t)((ng * 16 + (lane >> 4) * 8 + (lane & 7)) * 128
                                           + ((lane >> 3) & 1) * 16 + ks * 32));
                ldsm4(fh[ng], kbh + off);
                ldsm4(fl[ng], kbl + off);
            }
#pragma unroll
            for (int nt = 0; nt < 8; ++nt) {
                const uint32_t* bfh = &fh[nt >> 1][(nt & 1) * 2];
                const uint32_t* bfl = &fl[nt >> 1][(nt & 1) * 2];
                mma_bf16(s[nt], qfh[ks], bfh);
                mma_bf16(s[nt], qfh[ks], bfl);
                mma_bf16(s[nt], qfl[ks], bfh);
            }
        }

        // ---- online softmax in fragments (two row-halves per thread) ----
        float mx0 = -1.0e30f, mx1 = -1.0e30f;
#pragma unroll
        for (int nt = 0; nt < 8; ++nt) {
            mx0 = fmaxf(mx0, fmaxf(s[nt][0], s[nt][1]));
            mx1 = fmaxf(mx1, fmaxf(s[nt][2], s[nt][3]));
        }
        mx0 = fmaxf(mx0, __shfl_xor_sync(0xffffffffu, mx0, 1));
        mx0 = fmaxf(mx0, __shfl_xor_sync(0xffffffffu, mx0, 2));
        mx1 = fmaxf(mx1, __shfl_xor_sync(0xffffffffu, mx1, 1));
        mx1 = fmaxf(mx1, __shfl_xor_sync(0xffffffffu, mx1, 2));
        float mn0 = fmaxf(m0, mx0), mn1 = fmaxf(m1, mx1);
        float al0 = __expf(m0 - mn0), al1 = __expf(m1 - mn1);
        m0 = mn0; m1 = mn1;

        uint32_t paH[4][4], paL[4][4];
        float sum0 = 0.f, sum1 = 0.f;
#pragma unroll
        for (int nt = 0; nt < 8; ++nt) {
            float p0 = __expf(s[nt][0] - m0);
            float p1 = __expf(s[nt][1] - m0);
            float p2 = __expf(s[nt][2] - m1);
            float p3 = __expf(s[nt][3] - m1);
            sum0 += p0 + p1; sum1 += p2 + p3;
            __nv_bfloat16 h0 = __float2bfloat16(p0);
            __nv_bfloat16 h1 = __float2bfloat16(p1);
            __nv_bfloat16 h2 = __float2bfloat16(p2);
            __nv_bfloat16 h3 = __float2bfloat16(p3);
            int kc = nt >> 1;
            int ri = (nt & 1) * 2;
            paH[kc][ri]     = pack_bf16x2(h0, h1);
            paH[kc][ri + 1] = pack_bf16x2(h2, h3);
            paL[kc][ri]     = pack_bf16x2(__float2bfloat16(p0 - __bfloat162float(h0)),
                                          __float2bfloat16(p1 - __bfloat162float(h1)));
            paL[kc][ri + 1] = pack_bf16x2(__float2bfloat16(p2 - __bfloat162float(h2)),
                                          __float2bfloat16(p3 - __bfloat162float(h3)));
        }
        sum0 += __shfl_xor_sync(0xffffffffu, sum0, 1);
        sum0 += __shfl_xor_sync(0xffffffffu, sum0, 2);
        sum1 += __shfl_xor_sync(0xffffffffu, sum1, 1);
        sum1 += __shfl_xor_sync(0xffffffffu, sum1, 2);
        l0 = l0 * al0 + sum0;
        l1 = l1 * al1 + sum1;
#pragma unroll
        for (int dt = 0; dt < 8; ++dt) {
            o[dt][0] *= al0; o[dt][1] *= al0;
            o[dt][2] *= al1; o[dt][3] *= al1;
        }

        // ---- O += P V (V via ldmatrix.trans, 3-way split) ----
#pragma unroll
        for (int kc = 0; kc < 4; ++kc) {
            uint32_t vfh[4][4], vfl[4][4];
#pragma unroll
            for (int dg = 0; dg < 4; ++dg) {
                uint32_t off = SMEM_SWZ128((uint32_t)((kc * 16 + (lane & 7) + ((lane >> 3) & 1) * 8) * 128
                                           + dg * 32 + (lane >> 4) * 16));
                ldsm4t(vfh[dg], vbh + off);
                ldsm4t(vfl[dg], vbl + off);
            }
#pragma unroll
            for (int dt = 0; dt < 8; ++dt) {
                const uint32_t* bfh = &vfh[dt >> 1][(dt & 1) * 2];
                const uint32_t* bfl = &vfl[dt >> 1][(dt & 1) * 2];
                mma_bf16(o[dt], paH[kc], bfh);
                mma_bf16(o[dt], paH[kc], bfl);
                mma_bf16(o[dt], paL[kc], bfh);
            }
        }
    }

    // ---- normalize + store ----
    const int gq = lane >> 2;
    const int tq = lane & 3;
    const float inv0 = 1.0f / l0;
    const float inv1 = 1.0f / l1;
#pragma unroll
    for (int dt = 0; dt < 8; ++dt) {
        int col = hd * D_ + dt * 8 + tq * 2;
        size_t r0 = (size_t)(b * S_ + q0 + wm + gq);
        *(float2*)&attn[r0 * C_ + col] =
            make_float2(o[dt][0] * inv0, o[dt][1] * inv0);
        *(float2*)&attn[(r0 + 8) * C_ + col] =
            make_float2(o[dt][2] * inv1, o[dt][3] * inv1);
    }
}

// ---------------------------------------------------------------------------
// Launch
// ---------------------------------------------------------------------------
extern "C" void kernel_launch(void* const* d_in, const int* in_sizes, int n_in,
                              void* d_out, int out_size)
{
    (void)in_sizes; (void)n_in; (void)out_size;
    const float* hidden = (const float*)d_in[0];
    const float* cosp   = (const float*)d_in[1];
    const float* sinp   = (const float*)d_in[2];
    const float* qkv_w  = (const float*)d_in[3];
    const float* qkv_b  = (const float*)d_in[4];
    const float* proj_w = (const float*)d_in[5];
    const float* proj_b = (const float*)d_in[6];
    float* out = (float*)d_out;

    float *qkv_s, *attn_s;
    __nv_bfloat16 *hidH, *hidL, *qwH, *qwL, *pwH, *pwL, *atH, *atL;
    __nv_bfloat16 *fqh, *fql, *fkh, *fkl, *fvh, *fvl;
    cudaGetSymbolAddress((void**)&qkv_s,  g_qkv);
    cudaGetSymbolAddress((void**)&attn_s, g_attn);
    cudaGetSymbolAddress((void**)&hidH, g_hid_h);
    cudaGetSymbolAddress((void**)&hidL, g_hid_l);
    cudaGetSymbolAddress((void**)&qwH,  g_qw_h);
    cudaGetSymbolAddress((void**)&qwL,  g_qw_l);
    cudaGetSymbolAddress((void**)&pwH,  g_pw_h);
    cudaGetSymbolAddress((void**)&pwL,  g_pw_l);
    cudaGetSymbolAddress((void**)&atH,  g_at_h);
    cudaGetSymbolAddress((void**)&atL,  g_at_l);
    cudaGetSymbolAddress((void**)&fqh,  g_fqh);
    cudaGetSymbolAddress((void**)&fql,  g_fql);
    cudaGetSymbolAddress((void**)&fkh,  g_fkh);
    cudaGetSymbolAddress((void**)&fkl,  g_fkl);
    cudaGetSymbolAddress((void**)&fvh,  g_fvh);
    cudaGetSymbolAddress((void**)&fvl,  g_fvl);

    cudaFuncSetAttribute(mma_gemm_split,
                         cudaFuncAttributeMaxDynamicSharedMemorySize, MMA_SMEM_BYTES);
    cudaFuncSetAttribute(flash_mma_kernel,
                         cudaFuncAttributeMaxDynamicSharedMemorySize, FL_SMEM_BYTES);

    // 0) split inputs / weights to bf16 hi+lo
    split_bf16_kernel<<<(M_ * C_ / 4 + 255) / 256, 256>>>(hidden, hidH, hidL, M_ * C_);
    split_bf16_kernel<<<(3 * C_ * C_ / 4 + 255) / 256, 256>>>(qkv_w, qwH, qwL, 3 * C_ * C_);
    split_bf16_kernel<<<(C_ * C_ / 4 + 255) / 256, 256>>>(proj_w, pwH, pwL, C_ * C_);

    // 1) QKV GEMM (tensor cores, double-buffered)
    mma_gemm_split<<<dim3(3 * C_ / 128, M_ / 128), 256, MMA_SMEM_BYTES>>>(
        hidH, hidL, qwH, qwL, qkv_b, qkv_s, 3 * C_, C_);

    // 2) RoPE + split q/k/v to bf16 hi/lo row-major [bh][s][d]
    rope_split_kernel<<<dim3(M_, 3), 256>>>(
        qkv_s, cosp, sinp, fqh, fql, fkh, fkl, fvh, fvl);

    // 3) Flash attention on tensor cores
    flash_mma_kernel<<<dim3(S_ / 128, 64), 256, FL_SMEM_BYTES>>>(
        fqh, fql, fkh, fkl, fvh, fvl, attn_s);

    // 4) split attn, proj GEMM
    split_bf16_kernel<<<(M_ * C_ / 4 + 255) / 256, 256>>>(attn_s, atH, atL, M_ * C_);
    mma_gemm_split<<<dim3(C_ / 128, M_ / 128), 256, MMA_SMEM_BYTES>>>(
        atH, atL, pwH, pwL, proj_b, out, C_, C_);
}